// round 9
// baseline (speedup 1.0000x reference)
#include <cuda_runtime.h>
#include <math.h>
#include <stdint.h>

#define NQ 16384
#define NC 8192
#define DD 256
#define ZELEMS 4194304
#define LOSS_OFF 4194304
#define PERP_OFF 4194305
#define UNIQ_OFF 4194306
#define IDX_OFF  4194307

// ---------------- device scratch ----------------
__device__ float g_wT[DD * NC];     // weight transposed [k][c]
__device__ float g_cnorm[NC];
__device__ int   g_counts[NC];
__device__ int   g_idx[NQ];
__device__ float g_lpart[16384];
__device__ float g_hs[2 * NQ];      // per-half best score
__device__ int   g_hi[2 * NQ];      // per-half best index

// ---------------- prep ----------------
__global__ void k_zero() {
    int t = blockIdx.x * blockDim.x + threadIdx.x;
    if (t < NC) g_counts[t] = 0;
}

__global__ void k_transpose(const float* __restrict__ w) {
    __shared__ float tile[32][33];
    int c0 = blockIdx.x * 32, k0 = blockIdx.y * 32;
    int tx = threadIdx.x, ty = threadIdx.y;
#pragma unroll
    for (int r = 0; r < 4; r++)
        tile[ty + r * 8][tx] = w[(c0 + ty + r * 8) * DD + k0 + tx];
    __syncthreads();
#pragma unroll
    for (int r = 0; r < 4; r++)
        g_wT[(k0 + ty + r * 8) * NC + c0 + tx] = tile[tx][ty + r * 8];
}

__global__ void k_cnorm(const float* __restrict__ w) {
    int warp = threadIdx.x >> 5, lane = threadIdx.x & 31;
    int c = blockIdx.x * 8 + warp;
    const float* row = w + c * DD;
    float s = 0.f;
#pragma unroll
    for (int j = 0; j < 8; j++) { float v = row[lane + j * 32]; s += v * v; }
#pragma unroll
    for (int off = 16; off; off >>= 1) s += __shfl_xor_sync(0xffffffffu, s, off);
    if (lane == 0) g_cnorm[c] = s;
}

// ---------------- FFMA2 helpers ----------------
__device__ __forceinline__ void ffma2(unsigned long long& acc,
                                      unsigned long long a, unsigned long long b) {
    asm("fma.rn.f32x2 %0, %1, %2, %0;" : "+l"(acc) : "l"(a), "l"(b));
}
__device__ __forceinline__ float f2lo(unsigned long long v) {
    return __uint_as_float((unsigned)(v & 0xffffffffu));
}
__device__ __forceinline__ float f2hi(unsigned long long v) {
    return __uint_as_float((unsigned)(v >> 32));
}

// smem: Q [16][256] float2 x2 buf = 64K | C [16][128] float x2 buf = 16K
#define SM_Q 0
#define SM_C 65536
#define SMEM_SZ 81920

// ---------------- exact argmin GEMM (FFMA2, 512 thr, half codebook per CTA) ----
// grid 128 = 64 query-slabs (256 q) x 2 code halves (4096 c)
__global__ void __launch_bounds__(512, 1) k_argmin(const float* __restrict__ z) {
    extern __shared__ char smem[];

    int tid = threadIdx.x;
    int tx = tid & 7, ty = tid >> 3;             // tx: 16-code group, ty: 4-query group
    int qt = blockIdx.x >> 1, half = blockIdx.x & 1;
    int cb = half * 4096;
    int b = qt >> 4, s0 = (qt & 15) * 256;
    const float* zb = z + b * 1048576 + s0;

    // fill-unit mapping (1024 quad-units for Q slice, 512 float4 for C slice)
    int kkq0 = tid >> 6, qq0 = (tid & 63) * 4;
    int kkq1 = (tid + 512) >> 6, qq1 = ((tid + 512) & 63) * 4;
    int kkc = tid >> 5, cc = (tid & 31) * 4;

    unsigned long long acc[4][8];
#pragma unroll
    for (int i = 0; i < 4; i++)
#pragma unroll
        for (int j = 0; j < 8; j++) acc[i][j] = 0ULL;

    float bs[4];
    int   bi[4];
#pragma unroll
    for (int i = 0; i < 4; i++) { bs[i] = __int_as_float(0x7f800000); bi[i] = 0; }

    float4 pq0, pq1, pc;
    // prefetch m=0
    pq0 = *(const float4*)(zb + kkq0 * 4096 + qq0);
    pq1 = *(const float4*)(zb + kkq1 * 4096 + qq1);
    pc  = *(const float4*)(g_wT + kkc * NC + cb + cc);

    int buf = 0;
    {
        float4* qd = (float4*)(smem + SM_Q + kkq0 * 2048 + qq0 * 8);
        qd[0] = make_float4(pq0.x, pq0.x, pq0.y, pq0.y);
        qd[1] = make_float4(pq0.z, pq0.z, pq0.w, pq0.w);
        float4* qd1 = (float4*)(smem + SM_Q + kkq1 * 2048 + qq1 * 8);
        qd1[0] = make_float4(pq1.x, pq1.x, pq1.y, pq1.y);
        qd1[1] = make_float4(pq1.z, pq1.z, pq1.w, pq1.w);
        *(float4*)(smem + SM_C + kkc * 512 + cc * 4) = pc;
    }
    __syncthreads();

    int qoff = ty * 32;                          // ty*4 queries * 8 bytes
    int coff = tx * 64;                          // tx*16 codes * 4 bytes  (R8 bug: was *128)

    for (int m = 0; m < 512; m++) {              // 32 code tiles x 16 k-chunks
        if (m + 1 < 512) {
            int k0 = ((m + 1) & 15) * 16;
            int c0 = ((m + 1) >> 4) * 128;
            pq0 = *(const float4*)(zb + (k0 + kkq0) * 4096 + qq0);
            pq1 = *(const float4*)(zb + (k0 + kkq1) * 4096 + qq1);
            pc  = *(const float4*)(g_wT + (k0 + kkc) * NC + cb + c0 + cc);
        }
        const char* Qb = smem + SM_Q + buf * 32768;
        const char* Cb = smem + SM_C + buf * 8192;
#pragma unroll
        for (int kk = 0; kk < 16; kk++) {
            const char* qr = Qb + kk * 2048 + qoff;
            const char* cr = Cb + kk * 512 + coff;
            ulonglong2 qa01 = *(const ulonglong2*)qr;
            ulonglong2 qa23 = *(const ulonglong2*)(qr + 16);
            ulonglong2 cp01 = *(const ulonglong2*)cr;
            ulonglong2 cp23 = *(const ulonglong2*)(cr + 16);
            ulonglong2 cp45 = *(const ulonglong2*)(cr + 32);
            ulonglong2 cp67 = *(const ulonglong2*)(cr + 48);
            unsigned long long qa[4] = {qa01.x, qa01.y, qa23.x, qa23.y};
            unsigned long long cp[8] = {cp01.x, cp01.y, cp23.x, cp23.y,
                                        cp45.x, cp45.y, cp67.x, cp67.y};
#pragma unroll
            for (int i = 0; i < 4; i++)
#pragma unroll
                for (int j = 0; j < 8; j++)
                    ffma2(acc[i][j], qa[i], cp[j]);
        }
        if ((m & 15) == 15) {                    // code tile done: score + reset
            int cbase = cb + (m >> 4) * 128 + tx * 16;
            float cn[16];
#pragma unroll
            for (int u = 0; u < 4; u++)
                *(float4*)&cn[u * 4] = __ldg((const float4*)(g_cnorm + cbase + u * 4));
#pragma unroll
            for (int i = 0; i < 4; i++) {
#pragma unroll
                for (int j = 0; j < 8; j++) {
                    float slo = cn[2 * j]     - 2.f * f2lo(acc[i][j]);
                    float shi = cn[2 * j + 1] - 2.f * f2hi(acc[i][j]);
                    if (slo < bs[i]) { bs[i] = slo; bi[i] = cbase + 2 * j; }
                    if (shi < bs[i]) { bs[i] = shi; bi[i] = cbase + 2 * j + 1; }
                    acc[i][j] = 0ULL;
                }
            }
        }
        if (m + 1 < 512) {
            char* Qn = smem + SM_Q + (buf ^ 1) * 32768;
            char* Cn = smem + SM_C + (buf ^ 1) * 8192;
            float4* qd = (float4*)(Qn + kkq0 * 2048 + qq0 * 8);
            qd[0] = make_float4(pq0.x, pq0.x, pq0.y, pq0.y);
            qd[1] = make_float4(pq0.z, pq0.z, pq0.w, pq0.w);
            float4* qd1 = (float4*)(Qn + kkq1 * 2048 + qq1 * 8);
            qd1[0] = make_float4(pq1.x, pq1.x, pq1.y, pq1.y);
            qd1[1] = make_float4(pq1.z, pq1.z, pq1.w, pq1.w);
            *(float4*)(Cn + kkc * 512 + cc * 4) = pc;
            __syncthreads();
            buf ^= 1;
        }
    }

    // reduce over 8 tx lanes (xor 4,2,1 stays inside the 8-lane group)
#pragma unroll
    for (int i = 0; i < 4; i++) {
        float s = bs[i]; int ci = bi[i];
#pragma unroll
        for (int off = 4; off; off >>= 1) {
            float so = __shfl_xor_sync(0xffffffffu, s, off);
            int   co = __shfl_xor_sync(0xffffffffu, ci, off);
            if (so < s || (so == s && co < ci)) { s = so; ci = co; }
        }
        if (tx == 0) {
            int q = qt * 256 + ty * 4 + i;
            g_hs[half * NQ + q] = s;
            g_hi[half * NQ + q] = ci;
        }
    }
}

// ---------------- merge halves + histogram ----------------
__global__ void k_merge() {
    int q = blockIdx.x * 256 + threadIdx.x;
    float s0 = g_hs[q], s1 = g_hs[NQ + q];
    int i0 = g_hi[q], i1 = g_hi[NQ + q];
    int bi = (s1 < s0) ? i1 : i0;        // tie keeps half 0 (lower indices)
    g_idx[q] = bi;
    atomicAdd(&g_counts[bi], 1);
}

// ---------------- gather + straight-through + loss partials ----------------
__global__ void k_gather(const float* __restrict__ z, const float* __restrict__ w,
                         float* __restrict__ out) {
    int o = blockIdx.x * 256 + threadIdx.x;
    int s = o & 4095;
    int c = (o >> 12) & 255;
    int b = o >> 20;
    int n = b * 4096 + s;
    int id = g_idx[n];
    float zv = z[o];
    float wv = __ldg(w + id * DD + c);
    float d = wv - zv;
    out[o] = zv + d;

    float v = d * d;
#pragma unroll
    for (int off = 16; off; off >>= 1) v += __shfl_xor_sync(0xffffffffu, v, off);
    __shared__ float red[8];
    if ((threadIdx.x & 31) == 0) red[threadIdx.x >> 5] = v;
    __syncthreads();
    if (threadIdx.x == 0) {
        float tsum = 0.f;
#pragma unroll
        for (int i = 0; i < 8; i++) tsum += red[i];
        g_lpart[blockIdx.x] = tsum;
    }
}

__global__ void k_idxout(float* __restrict__ out) {
    int t = blockIdx.x * blockDim.x + threadIdx.x;
    if (t < NQ) out[IDX_OFF + t] = (float)g_idx[t];
}

__global__ void k_final(float* __restrict__ out) {
    __shared__ double ds[32];
    __shared__ float es[32];
    __shared__ int us[32];
    int t = threadIdx.x, lane = t & 31, warp = t >> 5;

    double lsum = 0.0;
    for (int i = t; i < 16384; i += 1024) lsum += (double)g_lpart[i];

    float ent = 0.f; int uniq = 0;
    for (int c = t; c < NC; c += 1024) {
        int cnt = g_counts[c];
        float p = (float)cnt * (1.0f / 16384.0f);
        ent += p * logf(p + 1e-10f);
        uniq += (cnt > 0);
    }
#pragma unroll
    for (int off = 16; off; off >>= 1) {
        lsum += __shfl_xor_sync(0xffffffffu, lsum, off);
        ent += __shfl_xor_sync(0xffffffffu, ent, off);
        uniq += __shfl_xor_sync(0xffffffffu, uniq, off);
    }
    if (lane == 0) { ds[warp] = lsum; es[warp] = ent; us[warp] = uniq; }
    __syncthreads();
    if (t == 0) {
        double L = 0.0; float E = 0.f; int U = 0;
        for (int i = 0; i < 32; i++) { L += ds[i]; E += es[i]; U += us[i]; }
        out[LOSS_OFF] = 0.25f * (float)(L * (1.0 / 4194304.0));
        out[PERP_OFF] = expf(-E);
        out[UNIQ_OFF] = (float)U;
    }
}

// ---------------- launch ----------------
extern "C" void kernel_launch(void* const* d_in, const int* in_sizes, int n_in,
                              void* d_out, int out_size) {
    const float* z = (const float*)d_in[0];
    const float* w = (const float*)d_in[1];
    float* out = (float*)d_out;

    cudaFuncSetAttribute(k_argmin, cudaFuncAttributeMaxDynamicSharedMemorySize, SMEM_SZ);

    k_zero<<<8, 1024>>>();
    k_transpose<<<dim3(NC / 32, DD / 32), dim3(32, 8)>>>(w);
    k_cnorm<<<NC / 8, 256>>>(w);
    k_argmin<<<128, 512, SMEM_SZ>>>(z);
    k_merge<<<NQ / 256, 256>>>();
    k_gather<<<ZELEMS / 256, 256>>>(z, w, out);
    k_idxout<<<16, 1024>>>(out);
    k_final<<<1, 1024>>>(out);
}

// round 10
// speedup vs baseline: 1.6011x; 1.6011x over previous
#include <cuda_runtime.h>
#include <math.h>
#include <stdint.h>

#define NQ 16384
#define NC 8192
#define DD 256
#define ZELEMS 4194304
#define LOSS_OFF 4194304
#define PERP_OFF 4194305
#define UNIQ_OFF 4194306
#define IDX_OFF  4194307

// ---------------- device scratch ----------------
__device__ float g_wT[DD * NC];     // weight transposed [k][c]
__device__ float g_cnorm[NC];
__device__ int   g_counts[NC];
__device__ int   g_idx[NQ];
__device__ float g_lpart[16384];
__device__ float g_hs[2 * NQ];      // per-half best score
__device__ int   g_hi[2 * NQ];      // per-half best index

// ---------------- prep ----------------
__global__ void k_zero() {
    int t = blockIdx.x * blockDim.x + threadIdx.x;
    if (t < NC) g_counts[t] = 0;
}

__global__ void k_transpose(const float* __restrict__ w) {
    __shared__ float tile[32][33];
    int c0 = blockIdx.x * 32, k0 = blockIdx.y * 32;
    int tx = threadIdx.x, ty = threadIdx.y;
#pragma unroll
    for (int r = 0; r < 4; r++)
        tile[ty + r * 8][tx] = w[(c0 + ty + r * 8) * DD + k0 + tx];
    __syncthreads();
#pragma unroll
    for (int r = 0; r < 4; r++)
        g_wT[(k0 + ty + r * 8) * NC + c0 + tx] = tile[tx][ty + r * 8];
}

__global__ void k_cnorm(const float* __restrict__ w) {
    int warp = threadIdx.x >> 5, lane = threadIdx.x & 31;
    int c = blockIdx.x * 8 + warp;
    const float* row = w + c * DD;
    float s = 0.f;
#pragma unroll
    for (int j = 0; j < 8; j++) { float v = row[lane + j * 32]; s += v * v; }
#pragma unroll
    for (int off = 16; off; off >>= 1) s += __shfl_xor_sync(0xffffffffu, s, off);
    if (lane == 0) g_cnorm[c] = s;
}

// ---------------- FFMA2 helpers ----------------
__device__ __forceinline__ void ffma2(unsigned long long& acc,
                                      unsigned long long a, unsigned long long b) {
    asm("fma.rn.f32x2 %0, %1, %2, %0;" : "+l"(acc) : "l"(a), "l"(b));
}
__device__ __forceinline__ float f2lo(unsigned long long v) {
    return __uint_as_float((unsigned)(v & 0xffffffffu));
}
__device__ __forceinline__ float f2hi(unsigned long long v) {
    return __uint_as_float((unsigned)(v >> 32));
}

// smem: Q [16][256] float2 x2 buf = 64K | C [16][128] float x2 buf = 16K
#define SM_Q 0
#define SM_C 65536
#define SMEM_SZ 81920

// C column permutation inside one 512B k-row: code c -> (c>>5)*128 + ((c>>2)&7)*16 + (c&3)*4
__device__ __forceinline__ int cperm(int c) {
    return ((c >> 5) << 7) + (((c >> 2) & 7) << 4) + ((c & 3) << 2);
}

// ---------------- exact argmin GEMM (FFMA2, 512 thr, half codebook per CTA) ----
// grid 128 = 64 query-slabs (256 q) x 2 code halves (4096 c)
__global__ void __launch_bounds__(512, 1) k_argmin(const float* __restrict__ z) {
    extern __shared__ char smem[];

    int tid = threadIdx.x;
    int tx = tid & 7, ty = tid >> 3;             // tx: code group, ty: 4-query group
    int qt = blockIdx.x >> 1, half = blockIdx.x & 1;
    int cb = half * 4096;
    int b = qt >> 4, s0 = (qt & 15) * 256;
    const float* zb = z + b * 1048576 + s0;

    // fill-unit mapping
    int kkq0 = tid >> 6, qq0 = (tid & 63) * 4;
    int kkq1 = (tid + 512) >> 6, qq1 = ((tid + 512) & 63) * 4;
    int kkc = tid >> 5, cc = (tid & 31) * 4;
    int ccp = cperm(cc);                          // 16B-aligned (cc mult of 4)

    unsigned long long acc[4][8];
#pragma unroll
    for (int i = 0; i < 4; i++)
#pragma unroll
        for (int j = 0; j < 8; j++) acc[i][j] = 0ULL;

    float bs[4];
    int   bi[4];
#pragma unroll
    for (int i = 0; i < 4; i++) { bs[i] = __int_as_float(0x7f800000); bi[i] = 0; }

    float4 pq0, pq1, pc;
    pq0 = *(const float4*)(zb + kkq0 * 4096 + qq0);
    pq1 = *(const float4*)(zb + kkq1 * 4096 + qq1);
    pc  = *(const float4*)(g_wT + kkc * NC + cb + cc);

    int buf = 0;
    {
        float4* qd = (float4*)(smem + SM_Q + kkq0 * 2048 + qq0 * 8);
        qd[0] = make_float4(pq0.x, pq0.x, pq0.y, pq0.y);
        qd[1] = make_float4(pq0.z, pq0.z, pq0.w, pq0.w);
        float4* qd1 = (float4*)(smem + SM_Q + kkq1 * 2048 + qq1 * 8);
        qd1[0] = make_float4(pq1.x, pq1.x, pq1.y, pq1.y);
        qd1[1] = make_float4(pq1.z, pq1.z, pq1.w, pq1.w);
        *(float4*)(smem + SM_C + kkc * 512 + ccp) = pc;
    }
    __syncthreads();

    int qoff = ty * 32;                          // ty*4 queries * 8 bytes
    int coff = tx * 16;                          // within each 128B j-block

    for (int m = 0; m < 512; m++) {              // 32 code tiles x 16 k-chunks
        if (m + 1 < 512) {
            int k0 = ((m + 1) & 15) * 16;
            int c0 = ((m + 1) >> 4) * 128;
            pq0 = *(const float4*)(zb + (k0 + kkq0) * 4096 + qq0);
            pq1 = *(const float4*)(zb + (k0 + kkq1) * 4096 + qq1);
            pc  = *(const float4*)(g_wT + (k0 + kkc) * NC + cb + c0 + cc);
        }
        const char* Qb = smem + SM_Q + buf * 32768;
        const char* Cb = smem + SM_C + buf * 8192;
#pragma unroll
        for (int kk = 0; kk < 16; kk++) {
            const char* qr = Qb + kk * 2048 + qoff;
            const char* cr = Cb + kk * 512 + coff;
            ulonglong2 qa01 = *(const ulonglong2*)qr;
            ulonglong2 qa23 = *(const ulonglong2*)(qr + 16);
            ulonglong2 cj0 = *(const ulonglong2*)cr;           // j=0: codes tx*4+0..3
            ulonglong2 cj1 = *(const ulonglong2*)(cr + 128);   // j=1
            ulonglong2 cj2 = *(const ulonglong2*)(cr + 256);   // j=2
            ulonglong2 cj3 = *(const ulonglong2*)(cr + 384);   // j=3
            unsigned long long qa[4] = {qa01.x, qa01.y, qa23.x, qa23.y};
            unsigned long long cp[8] = {cj0.x, cj0.y, cj1.x, cj1.y,
                                        cj2.x, cj2.y, cj3.x, cj3.y};
#pragma unroll
            for (int i = 0; i < 4; i++)
#pragma unroll
                for (int j = 0; j < 8; j++)
                    ffma2(acc[i][j], qa[i], cp[j]);
        }
        if ((m & 15) == 15) {                    // code tile done: score + reset
            // thread's codes: cb + tile*128 + j*32 + tx*4 + u  (j=0..3, u=0..3)
            int cbase = cb + (m >> 4) * 128 + tx * 4;
            float cn[16];
#pragma unroll
            for (int u = 0; u < 4; u++)
                *(float4*)&cn[u * 4] = __ldg((const float4*)(g_cnorm + cbase + u * 32));
#pragma unroll
            for (int i = 0; i < 4; i++) {
#pragma unroll
                for (int j = 0; j < 4; j++) {
                    int id0 = cbase + j * 32;
                    float sa = cn[4 * j]     - 2.f * f2lo(acc[i][2 * j]);
                    float sb2 = cn[4 * j + 1] - 2.f * f2hi(acc[i][2 * j]);
                    float sc = cn[4 * j + 2] - 2.f * f2lo(acc[i][2 * j + 1]);
                    float sd = cn[4 * j + 3] - 2.f * f2hi(acc[i][2 * j + 1]);
                    if (sa < bs[i]) { bs[i] = sa; bi[i] = id0; }
                    if (sb2 < bs[i]) { bs[i] = sb2; bi[i] = id0 + 1; }
                    if (sc < bs[i]) { bs[i] = sc; bi[i] = id0 + 2; }
                    if (sd < bs[i]) { bs[i] = sd; bi[i] = id0 + 3; }
                    acc[i][2 * j] = 0ULL;
                    acc[i][2 * j + 1] = 0ULL;
                }
            }
        }
        if (m + 1 < 512) {
            char* Qn = smem + SM_Q + (buf ^ 1) * 32768;
            char* Cn = smem + SM_C + (buf ^ 1) * 8192;
            float4* qd = (float4*)(Qn + kkq0 * 2048 + qq0 * 8);
            qd[0] = make_float4(pq0.x, pq0.x, pq0.y, pq0.y);
            qd[1] = make_float4(pq0.z, pq0.z, pq0.w, pq0.w);
            float4* qd1 = (float4*)(Qn + kkq1 * 2048 + qq1 * 8);
            qd1[0] = make_float4(pq1.x, pq1.x, pq1.y, pq1.y);
            qd1[1] = make_float4(pq1.z, pq1.z, pq1.w, pq1.w);
            *(float4*)(Cn + kkc * 512 + ccp) = pc;
            __syncthreads();
            buf ^= 1;
        }
    }

    // reduce over 8 tx lanes; ties -> lowest index (matches reference argmin)
#pragma unroll
    for (int i = 0; i < 4; i++) {
        float s = bs[i]; int ci = bi[i];
#pragma unroll
        for (int off = 4; off; off >>= 1) {
            float so = __shfl_xor_sync(0xffffffffu, s, off);
            int   co = __shfl_xor_sync(0xffffffffu, ci, off);
            if (so < s || (so == s && co < ci)) { s = so; ci = co; }
        }
        if (tx == 0) {
            int q = qt * 256 + ty * 4 + i;
            g_hs[half * NQ + q] = s;
            g_hi[half * NQ + q] = ci;
        }
    }
}

// ---------------- merge halves + histogram ----------------
__global__ void k_merge() {
    int q = blockIdx.x * 256 + threadIdx.x;
    float s0 = g_hs[q], s1 = g_hs[NQ + q];
    int i0 = g_hi[q], i1 = g_hi[NQ + q];
    int bi = (s1 < s0) ? i1 : i0;        // tie keeps half 0 (lower indices)
    g_idx[q] = bi;
    atomicAdd(&g_counts[bi], 1);
}

// ---------------- gather + straight-through + loss partials ----------------
__global__ void k_gather(const float* __restrict__ z, const float* __restrict__ w,
                         float* __restrict__ out) {
    int o = blockIdx.x * 256 + threadIdx.x;
    int s = o & 4095;
    int c = (o >> 12) & 255;
    int b = o >> 20;
    int n = b * 4096 + s;
    int id = g_idx[n];
    float zv = z[o];
    float wv = __ldg(w + id * DD + c);
    float d = wv - zv;
    out[o] = zv + d;

    float v = d * d;
#pragma unroll
    for (int off = 16; off; off >>= 1) v += __shfl_xor_sync(0xffffffffu, v, off);
    __shared__ float red[8];
    if ((threadIdx.x & 31) == 0) red[threadIdx.x >> 5] = v;
    __syncthreads();
    if (threadIdx.x == 0) {
        float tsum = 0.f;
#pragma unroll
        for (int i = 0; i < 8; i++) tsum += red[i];
        g_lpart[blockIdx.x] = tsum;
    }
}

__global__ void k_idxout(float* __restrict__ out) {
    int t = blockIdx.x * blockDim.x + threadIdx.x;
    if (t < NQ) out[IDX_OFF + t] = (float)g_idx[t];
}

__global__ void k_final(float* __restrict__ out) {
    __shared__ double ds[32];
    __shared__ float es[32];
    __shared__ int us[32];
    int t = threadIdx.x, lane = t & 31, warp = t >> 5;

    double lsum = 0.0;
    for (int i = t; i < 16384; i += 1024) lsum += (double)g_lpart[i];

    float ent = 0.f; int uniq = 0;
    for (int c = t; c < NC; c += 1024) {
        int cnt = g_counts[c];
        float p = (float)cnt * (1.0f / 16384.0f);
        ent += p * logf(p + 1e-10f);
        uniq += (cnt > 0);
    }
#pragma unroll
    for (int off = 16; off; off >>= 1) {
        lsum += __shfl_xor_sync(0xffffffffu, lsum, off);
        ent += __shfl_xor_sync(0xffffffffu, ent, off);
        uniq += __shfl_xor_sync(0xffffffffu, uniq, off);
    }
    if (lane == 0) { ds[warp] = lsum; es[warp] = ent; us[warp] = uniq; }
    __syncthreads();
    if (t == 0) {
        double L = 0.0; float E = 0.f; int U = 0;
        for (int i = 0; i < 32; i++) { L += ds[i]; E += es[i]; U += us[i]; }
        out[LOSS_OFF] = 0.25f * (float)(L * (1.0 / 4194304.0));
        out[PERP_OFF] = expf(-E);
        out[UNIQ_OFF] = (float)U;
    }
}

// ---------------- launch ----------------
extern "C" void kernel_launch(void* const* d_in, const int* in_sizes, int n_in,
                              void* d_out, int out_size) {
    const float* z = (const float*)d_in[0];
    const float* w = (const float*)d_in[1];
    float* out = (float*)d_out;

    cudaFuncSetAttribute(k_argmin, cudaFuncAttributeMaxDynamicSharedMemorySize, SMEM_SZ);

    k_zero<<<8, 1024>>>();
    k_transpose<<<dim3(NC / 32, DD / 32), dim3(32, 8)>>>(w);
    k_cnorm<<<NC / 8, 256>>>(w);
    k_argmin<<<128, 512, SMEM_SZ>>>(z);
    k_merge<<<NQ / 256, 256>>>();
    k_gather<<<ZELEMS / 256, 256>>>(z, w, out);
    k_idxout<<<16, 1024>>>(out);
    k_final<<<1, 1024>>>(out);
}

// round 12
// speedup vs baseline: 3.2435x; 2.0258x over previous
#include <cuda_runtime.h>
#include <cuda_bf16.h>
#include <math.h>
#include <stdint.h>

#define NQ 16384
#define NC 8192
#define DD 256
#define ZELEMS 4194304
#define LOSS_OFF 4194304
#define PERP_OFF 4194305
#define UNIQ_OFF 4194306
#define IDX_OFF  4194307
#define NSM 148

// ---------------- device scratch ----------------
__device__ float          g_cnorm[NC];
__device__ int            g_counts[NC];
__device__ int            g_idx[NQ];
__device__ float          g_lpart[16384];
__device__ __nv_bfloat16  g_wB[NC * DD];          // bf16 codebook [code][k]
__device__ unsigned char  g_zB[128 * 65536];      // pre-swizzled bf16 A tiles per qslab
__device__ float          g_zT[NQ * DD];          // channel-last queries (rescore)
__device__ float          g_bm8[1024 * NQ];       // per-8-code bin minima, bin-major

// ---------------- PTX helpers ----------------
__device__ __forceinline__ uint32_t s2u(const void* p) {
    uint32_t a;
    asm("{ .reg .u64 t; cvta.to.shared.u64 t, %1; cvt.u32.u64 %0, t; }" : "=r"(a) : "l"(p));
    return a;
}
__device__ __forceinline__ void ldsm4(uint32_t addr, uint32_t& r0, uint32_t& r1,
                                      uint32_t& r2, uint32_t& r3) {
    asm volatile("ldmatrix.sync.aligned.m8n8.x4.shared.b16 {%0,%1,%2,%3}, [%4];"
                 : "=r"(r0), "=r"(r1), "=r"(r2), "=r"(r3) : "r"(addr));
}
__device__ __forceinline__ void mma16816(float* d, const uint32_t* a, uint32_t b0, uint32_t b1) {
    asm volatile(
        "mma.sync.aligned.m16n8k16.row.col.f32.bf16.bf16.f32 "
        "{%0,%1,%2,%3},{%4,%5,%6,%7},{%8,%9},{%0,%1,%2,%3};"
        : "+f"(d[0]), "+f"(d[1]), "+f"(d[2]), "+f"(d[3])
        : "r"(a[0]), "r"(a[1]), "r"(a[2]), "r"(a[3]), "r"(b0), "r"(b1));
}
#define CPASYNC(dst, src) \
    asm volatile("cp.async.cg.shared.global [%0], [%1], 16;" :: "r"(dst), "l"(src))
#define CPCOMMIT() asm volatile("cp.async.commit_group;")
#define CPWAIT(n)  asm volatile("cp.async.wait_group %0;" :: "n"(n))

// smem: A 64K | B0 64K | B1 64K | cn 32K
#define SM_A  0
#define SM_B0 65536
#define SM_B1 131072
#define SM_CN 196608
#define SMEM_SZ 229376

// ---------------- prep ----------------
__global__ void k_zero() {
    int t = blockIdx.x * blockDim.x + threadIdx.x;
    if (t < NC) g_counts[t] = 0;
}

__global__ void k_cnorm(const float* __restrict__ w) {
    int warp = threadIdx.x >> 5, lane = threadIdx.x & 31;
    int c = blockIdx.x * 8 + warp;
    const float* row = w + c * DD;
    float s = 0.f;
#pragma unroll
    for (int j = 0; j < 8; j++) { float v = row[lane + j * 32]; s += v * v; }
#pragma unroll
    for (int off = 16; off; off >>= 1) s += __shfl_xor_sync(0xffffffffu, s, off);
    if (lane == 0) g_cnorm[c] = s;
}

__global__ void k_wbf16(const float* __restrict__ w) {
    int t = blockIdx.x * 256 + threadIdx.x;
    g_wB[t] = __float2bfloat16(w[t]);
}

// fp32 channel-last copy for rescore
__global__ void k_zt(const float* __restrict__ z) {
    __shared__ float tile[32][33];
    int s0 = blockIdx.x * 32, c0 = blockIdx.y * 32, b = blockIdx.z;
    int tx = threadIdx.x, ty = threadIdx.y;
#pragma unroll
    for (int r = 0; r < 4; r++)
        tile[ty + r * 8][tx] = z[b * 1048576 + (c0 + ty + r * 8) * 4096 + s0 + tx];
    __syncthreads();
#pragma unroll
    for (int r = 0; r < 4; r++)
        g_zT[(b * 4096 + s0 + ty + r * 8) * DD + c0 + tx] = tile[tx][ty + r * 8];
}

// pre-swizzled bf16 A tiles: one 64KB image per 128-query slab
__global__ void k_zb(const float* __restrict__ z) {
    int qs = blockIdx.x;
    int b = qs >> 5, s0 = (qs & 31) * 128;
    const float* zb = z + b * 1048576 + s0;
    unsigned char* dst = g_zB + (size_t)qs * 65536;
    for (int e = threadIdx.x; e < 32768; e += 256) {
        int c = e >> 7, r = e & 127;
        float v = zb[c * 4096 + r];
        int off = r * 512 + ((((c >> 3) ^ (r & 7)) << 4)) + (c & 7) * 2;
        *(__nv_bfloat16*)(dst + off) = __float2bfloat16(v);
    }
}

// ---------------- persistent HMMA filter over 148 SMs ----------------
// 8192 jobs = 128 qslabs x 64 ctiles; strip per CTA.
__global__ void __launch_bounds__(256, 1) k_tc() {
    extern __shared__ char smem[];
    uint32_t sb = s2u(smem);
    float* cn_s = (float*)(smem + SM_CN);

    int tid = threadIdx.x, lane = tid & 31, wid = tid >> 5;
    int j0 = (int)(((long long)blockIdx.x * 8192) / NSM);
    int j1 = (int)(((long long)(blockIdx.x + 1) * 8192) / NSM);

    // cnorm -> smem (visible after first A-fill sync)
    {
        const float4* src = (const float4*)g_cnorm;
        float4* dstv = (float4*)cn_s;
        for (int i = tid; i < 2048; i += 256) dstv[i] = src[i];
    }

    int wm = (wid & 3) * 32, wn = (wid >> 2) * 64;
    int aRow = wm + (lane & 15);
    int aSw = lane & 7;
    int aKo = lane >> 4;
    int bN = wn + (lane & 7) + ((lane >> 4) << 3);
    int bKo = (lane >> 3) & 1;

    // prefetch B(j0)
    {
        const char* gs = (const char*)g_wB + (size_t)(j0 & 63) * 65536;
#pragma unroll
        for (int i = 0; i < 16; i++) {
            int e = tid + i * 256;
            int n = e >> 5, kc = e & 31;
            CPASYNC(sb + SM_B0 + n * 512 + ((kc ^ (n & 7)) << 4), gs + n * 512 + kc * 16);
        }
        CPCOMMIT();
    }

    int cur_q = -1, buf = 0;
    for (int jj = j0; jj < j1; jj++) {
        int q = jj >> 6, c = jj & 63;
        if (q != cur_q) {                       // A refill (rare: <=2 per CTA)
            const char* as = (const char*)g_zB + (size_t)q * 65536;
#pragma unroll
            for (int i = 0; i < 16; i++) {
                int e = tid + i * 256;
                CPASYNC(sb + SM_A + e * 16, as + (size_t)e * 16);
            }
            CPCOMMIT();
            CPWAIT(0);
            __syncthreads();
            cur_q = q;
        }
        if (jj + 1 < j1) {                      // prefetch next B
            const char* gs = (const char*)g_wB + (size_t)((jj + 1) & 63) * 65536;
            uint32_t bb = sb + ((buf ^ 1) ? SM_B1 : SM_B0);
#pragma unroll
            for (int i = 0; i < 16; i++) {
                int e = tid + i * 256;
                int n = e >> 5, kc = e & 31;
                CPASYNC(bb + n * 512 + ((kc ^ (n & 7)) << 4), gs + n * 512 + kc * 16);
            }
            CPCOMMIT();
            CPWAIT(1);
        } else {
            CPWAIT(0);
        }
        __syncthreads();

        uint32_t sB = sb + (buf ? SM_B1 : SM_B0);
        float d[2][8][4];
#pragma unroll
        for (int mi = 0; mi < 2; mi++)
#pragma unroll
            for (int ni = 0; ni < 8; ni++)
#pragma unroll
                for (int u = 0; u < 4; u++) d[mi][ni][u] = 0.f;

#pragma unroll 4
        for (int ks = 0; ks < 16; ks++) {
            int kkA = 2 * ks + aKo;
            uint32_t a0[4], a1[4];
            ldsm4(sb + SM_A + aRow * 512 + ((kkA ^ aSw) << 4), a0[0], a0[1], a0[2], a0[3]);
            ldsm4(sb + SM_A + (aRow + 16) * 512 + ((kkA ^ aSw) << 4), a1[0], a1[1], a1[2], a1[3]);
            int kkB = 2 * ks + bKo;
#pragma unroll
            for (int nb = 0; nb < 4; nb++) {
                int n = bN + nb * 16;
                uint32_t b0, b1, b2, b3;
                ldsm4(sB + n * 512 + ((kkB ^ (lane & 7)) << 4), b0, b1, b2, b3);
                mma16816(d[0][nb * 2], a0, b0, b1);
                mma16816(d[0][nb * 2 + 1], a0, b2, b3);
                mma16816(d[1][nb * 2], a1, b0, b1);
                mma16816(d[1][nb * 2 + 1], a1, b2, b3);
            }
        }

        // epilogue: dist = cn - 2*dot; per-8-col bin min; lanes%4==0 write
        int qbase = q * 128;
#pragma unroll
        for (int mi = 0; mi < 2; mi++) {
#pragma unroll
            for (int ni = 0; ni < 8; ni++) {
                float2 cn2 = *(float2*)&cn_s[c * 128 + wn + ni * 8 + (lane & 3) * 2];
                float v0 = fminf(cn2.x - 2.f * d[mi][ni][0], cn2.y - 2.f * d[mi][ni][1]);
                float v1 = fminf(cn2.x - 2.f * d[mi][ni][2], cn2.y - 2.f * d[mi][ni][3]);
                v0 = fminf(v0, __shfl_xor_sync(0xffffffffu, v0, 1));
                v0 = fminf(v0, __shfl_xor_sync(0xffffffffu, v0, 2));
                v1 = fminf(v1, __shfl_xor_sync(0xffffffffu, v1, 1));
                v1 = fminf(v1, __shfl_xor_sync(0xffffffffu, v1, 2));
                if ((lane & 3) == 0) {
                    int bin = c * 16 + (wn >> 3) + ni;
                    int q0 = qbase + wm + mi * 16 + (lane >> 2);
                    g_bm8[(size_t)bin * NQ + q0] = v0;
                    g_bm8[(size_t)bin * NQ + q0 + 8] = v1;
                }
            }
        }
        __syncthreads();
        buf ^= 1;
    }
}

// ---------------- exact rescore of candidate bins (+ idx output) ----------------
__global__ void k_rescore(const float* __restrict__ w, float* __restrict__ out) {
    int q = blockIdx.x * 128 + threadIdx.x;
    float m = __int_as_float(0x7f800000);
#pragma unroll 8
    for (int i = 0; i < 1024; i++) m = fminf(m, g_bm8[(size_t)i * NQ + q]);
    float thr = m + 2.0f;                        // covers bf16 approx error

    float best = __int_as_float(0x7f800000);
    int bi = 0;
    const float4* zq4 = (const float4*)(g_zT + (size_t)q * DD);
    for (int i = 0; i < 1024; i++) {
        if (g_bm8[(size_t)i * NQ + q] <= thr) {
            float acc[8];
#pragma unroll
            for (int k = 0; k < 8; k++) acc[k] = 0.f;
            const float4* wr = (const float4*)(w + (size_t)i * 8 * DD);
            for (int c4 = 0; c4 < 64; c4++) {
                float4 zv = __ldg(&zq4[c4]);
#pragma unroll
                for (int k = 0; k < 8; k++) {
                    float4 wv = __ldg(&wr[k * 64 + c4]);
                    acc[k] = fmaf(zv.x, wv.x, acc[k]);
                    acc[k] = fmaf(zv.y, wv.y, acc[k]);
                    acc[k] = fmaf(zv.z, wv.z, acc[k]);
                    acc[k] = fmaf(zv.w, wv.w, acc[k]);
                }
            }
#pragma unroll
            for (int k = 0; k < 8; k++) {
                int c = i * 8 + k;
                float sc = g_cnorm[c] - 2.f * acc[k];
                if (sc < best) { best = sc; bi = c; }
            }
        }
    }
    g_idx[q] = bi;
    out[IDX_OFF + q] = (float)bi;
    atomicAdd(&g_counts[bi], 1);
}

// ---------------- gather + straight-through + loss partials ----------------
__global__ void k_gather(const float* __restrict__ z, const float* __restrict__ w,
                         float* __restrict__ out) {
    int o = blockIdx.x * 256 + threadIdx.x;
    int s = o & 4095;
    int c = (o >> 12) & 255;
    int b = o >> 20;
    int n = b * 4096 + s;
    int id = g_idx[n];
    float zv = z[o];
    float wv = __ldg(w + id * DD + c);
    float d = wv - zv;
    out[o] = zv + d;

    float v = d * d;
#pragma unroll
    for (int off = 16; off; off >>= 1) v += __shfl_xor_sync(0xffffffffu, v, off);
    __shared__ float red[8];
    if ((threadIdx.x & 31) == 0) red[threadIdx.x >> 5] = v;
    __syncthreads();
    if (threadIdx.x == 0) {
        float tsum = 0.f;
#pragma unroll
        for (int i = 0; i < 8; i++) tsum += red[i];
        g_lpart[blockIdx.x] = tsum;
    }
}

__global__ void k_final(float* __restrict__ out) {
    __shared__ double ds[32];
    __shared__ float es[32];
    __shared__ int us[32];
    int t = threadIdx.x, lane = t & 31, warp = t >> 5;

    double lsum = 0.0;
    for (int i = t; i < 16384; i += 1024) lsum += (double)g_lpart[i];

    float ent = 0.f; int uniq = 0;
    for (int c = t; c < NC; c += 1024) {
        int cnt = g_counts[c];
        float p = (float)cnt * (1.0f / 16384.0f);
        ent += p * logf(p + 1e-10f);
        uniq += (cnt > 0);
    }
#pragma unroll
    for (int off = 16; off; off >>= 1) {
        lsum += __shfl_xor_sync(0xffffffffu, lsum, off);
        ent += __shfl_xor_sync(0xffffffffu, ent, off);
        uniq += __shfl_xor_sync(0xffffffffu, uniq, off);
    }
    if (lane == 0) { ds[warp] = lsum; es[warp] = ent; us[warp] = uniq; }
    __syncthreads();
    if (t == 0) {
        double L = 0.0; float E = 0.f; int U = 0;
        for (int i = 0; i < 32; i++) { L += ds[i]; E += es[i]; U += us[i]; }
        out[LOSS_OFF] = 0.25f * (float)(L * (1.0 / 4194304.0));
        out[PERP_OFF] = expf(-E);
        out[UNIQ_OFF] = (float)U;
    }
}

// ---------------- launch ----------------
extern "C" void kernel_launch(void* const* d_in, const int* in_sizes, int n_in,
                              void* d_out, int out_size) {
    const float* z = (const float*)d_in[0];
    const float* w = (const float*)d_in[1];
    float* out = (float*)d_out;

    cudaFuncSetAttribute(k_tc, cudaFuncAttributeMaxDynamicSharedMemorySize, SMEM_SZ);

    k_zero<<<8, 1024>>>();
    k_cnorm<<<NC / 8, 256>>>(w);
    k_wbf16<<<NC, 256>>>(w);
    k_zt<<<dim3(128, 8, 4), dim3(32, 8)>>>(z);
    k_zb<<<128, 256>>>(z);
    k_tc<<<NSM, 256, SMEM_SZ>>>();
    k_rescore<<<NQ / 128, 128>>>(w, out);
    k_gather<<<ZELEMS / 256, 256>>>(z, w, out);
    k_final<<<1, 1024>>>(out);
}